// round 1
// baseline (speedup 1.0000x reference)
#include <cuda_runtime.h>
#include <cstdint>

#define EMBED_DIM 64

// 16 threads cooperate on one edge; each lane handles 4 contiguous floats.
__global__ void __launch_bounds__(256)
spmm_scatter_kernel(const float* __restrict__ emb,
                    const float* __restrict__ vals,
                    const int*   __restrict__ rows,
                    const int*   __restrict__ cols,
                    float* __restrict__ out,
                    int n_edges)
{
    int t    = blockIdx.x * blockDim.x + threadIdx.x;
    int edge = t >> 4;          // 16 lanes per edge
    int lane = t & 15;
    if (edge >= n_edges) return;

    int   r = rows[edge];
    int   c = cols[edge];
    float v = vals[edge];

    const float4* src = reinterpret_cast<const float4*>(emb + (size_t)c * EMBED_DIM);
    float4 m = src[lane];
    m.x *= v; m.y *= v; m.z *= v; m.w *= v;

    float* dst = out + (size_t)r * EMBED_DIM + lane * 4;
    asm volatile("red.global.add.v4.f32 [%0], {%1, %2, %3, %4};"
                 :: "l"(dst), "f"(m.x), "f"(m.y), "f"(m.z), "f"(m.w)
                 : "memory");
}

extern "C" void kernel_launch(void* const* d_in, const int* in_sizes, int n_in,
                              void* d_out, int out_size)
{
    const float* emb  = (const float*)d_in[0];   // [N, 64] float32
    const float* vals = (const float*)d_in[1];   // [E]     float32
    const int*   rows = (const int*)  d_in[2];   // [E]     int32
    const int*   cols = (const int*)  d_in[3];   // [E]     int32
    float* out = (float*)d_out;                  // [N, 64] float32

    int n_edges = in_sizes[1];

    // d_out is poisoned; zero it first (memset node is graph-capturable).
    cudaMemsetAsync(out, 0, (size_t)out_size * sizeof(float), 0);

    int total_threads = n_edges * 16;
    int block = 256;
    int grid  = (total_threads + block - 1) / block;
    spmm_scatter_kernel<<<grid, block>>>(emb, vals, rows, cols, out, n_edges);
}

// round 3
// speedup vs baseline: 1.0770x; 1.0770x over previous
#include <cuda_runtime.h>
#include <cstdint>

#define EMBED_DIM 64
#define EDGES_PER_THREAD 4
// block = 256 threads = 16 edge-slots x 16 lanes; each slot handles 4 edges
#define EDGES_PER_BLOCK (16 * EDGES_PER_THREAD)   // 64

__global__ void __launch_bounds__(256)
spmm_scatter_kernel(const float* __restrict__ emb,
                    const float* __restrict__ vals,
                    const int*   __restrict__ rows,
                    const int*   __restrict__ cols,
                    float* __restrict__ out,
                    int n_edges)
{
    int lane = threadIdx.x & 15;        // 16 lanes per edge, 16B each
    int slot = threadIdx.x >> 4;        // 0..15
    int base = blockIdx.x * EDGES_PER_BLOCK + slot;

    int   r[EDGES_PER_THREAD];
    int   c[EDGES_PER_THREAD];
    float v[EDGES_PER_THREAD];
    bool  ok[EDGES_PER_THREAD];

    // Front-batch all edge-metadata loads (independent -> MLP)
    #pragma unroll
    for (int k = 0; k < EDGES_PER_THREAD; k++) {
        int e = base + k * 16;
        ok[k] = e < n_edges;
        int es = ok[k] ? e : 0;
        r[k] = rows[es];
        c[k] = cols[es];
        v[k] = vals[es];
    }

    // Front-batch all gather loads (independent -> MLP=4 on the L2 round-trip)
    float4 m[EDGES_PER_THREAD];
    #pragma unroll
    for (int k = 0; k < EDGES_PER_THREAD; k++) {
        const float4* src = reinterpret_cast<const float4*>(emb + (size_t)c[k] * EMBED_DIM);
        m[k] = src[lane];
    }

    // Scale + fire-and-forget reductions
    #pragma unroll
    for (int k = 0; k < EDGES_PER_THREAD; k++) {
        if (!ok[k]) continue;
        float4 t = m[k];
        t.x *= v[k]; t.y *= v[k]; t.z *= v[k]; t.w *= v[k];
        float* dst = out + (size_t)r[k] * EMBED_DIM + lane * 4;
        asm volatile("red.global.add.v4.f32 [%0], {%1, %2, %3, %4};"
                     :: "l"(dst), "f"(t.x), "f"(t.y), "f"(t.z), "f"(t.w)
                     : "memory");
    }
}

extern "C" void kernel_launch(void* const* d_in, const int* in_sizes, int n_in,
                              void* d_out, int out_size)
{
    const float* emb  = (const float*)d_in[0];   // [N, 64] float32
    const float* vals = (const float*)d_in[1];   // [E]     float32
    const int*   rows = (const int*)  d_in[2];   // [E]     int32
    const int*   cols = (const int*)  d_in[3];   // [E]     int32
    float* out = (float*)d_out;                  // [N, 64] float32

    int n_edges = in_sizes[1];

    cudaMemsetAsync(out, 0, (size_t)out_size * sizeof(float), 0);

    int grid = (n_edges + EDGES_PER_BLOCK - 1) / EDGES_PER_BLOCK;
    spmm_scatter_kernel<<<grid, 256>>>(emb, vals, rows, cols, out, n_edges);
}

// round 4
// speedup vs baseline: 1.1419x; 1.0603x over previous
#include <cuda_runtime.h>
#include <cstdint>

#define MAX_N 100000
#define MAX_E 1600000
#define D 64

// Device-global scratch (allocation-free per harness rules)
__device__ int  g_hist[MAX_N];       // per-row edge counts
__device__ int  g_off [MAX_N + 1];   // exclusive row offsets (CSR)
__device__ int  g_cur [MAX_N];       // scatter cursors
__device__ int  g_bsum[128];         // scan block sums
__device__ int  g_boff[128];         // scanned block sums
__device__ int2 g_pairs[MAX_E];      // row-sorted (col, val_bits)

// ---- Phase 1: zero histogram ----
__global__ void k_zero(int n) {
    for (int i = blockIdx.x * blockDim.x + threadIdx.x; i < n;
         i += gridDim.x * blockDim.x)
        g_hist[i] = 0;
}

// ---- Phase 2: histogram of rows ----
__global__ void k_hist(const int* __restrict__ rows, int nE) {
    for (int e = blockIdx.x * blockDim.x + threadIdx.x; e < nE;
         e += gridDim.x * blockDim.x)
        atomicAdd(&g_hist[rows[e]], 1);
}

// ---- Phase 3a: per-block exclusive scan (1024 elems/block) ----
__global__ void k_scanA(int n) {
    __shared__ int warp_sums[32];
    int i    = blockIdx.x * 1024 + threadIdx.x;
    int lane = threadIdx.x & 31;
    int wid  = threadIdx.x >> 5;

    int v = (i < n) ? g_hist[i] : 0;
    int x = v;
    #pragma unroll
    for (int d = 1; d < 32; d <<= 1) {
        int y = __shfl_up_sync(~0u, x, d);
        if (lane >= d) x += y;
    }
    if (lane == 31) warp_sums[wid] = x;
    __syncthreads();
    if (wid == 0) {
        int s = warp_sums[lane];
        #pragma unroll
        for (int d = 1; d < 32; d <<= 1) {
            int y = __shfl_up_sync(~0u, s, d);
            if (lane >= d) s += y;
        }
        warp_sums[lane] = s;
    }
    __syncthreads();

    int excl = (x - v) + (wid > 0 ? warp_sums[wid - 1] : 0);
    if (i < n) g_off[i] = excl;                   // block-local exclusive
    if (threadIdx.x == 0) g_bsum[blockIdx.x] = warp_sums[31];  // block total
}

// ---- Phase 3b: scan the block sums (single block, nblk <= 128) ----
__global__ void k_scanB(int nblk) {
    __shared__ int warp_sums[4];
    int t    = threadIdx.x;           // 128 threads
    int lane = t & 31;
    int wid  = t >> 5;
    int v = (t < nblk) ? g_bsum[t] : 0;
    int x = v;
    #pragma unroll
    for (int d = 1; d < 32; d <<= 1) {
        int y = __shfl_up_sync(~0u, x, d);
        if (lane >= d) x += y;
    }
    if (lane == 31) warp_sums[wid] = x;
    __syncthreads();
    int prefix = 0;
    for (int w = 0; w < wid; w++) prefix += warp_sums[w];
    if (t < 128) g_boff[t] = prefix + (x - v);
}

// ---- Phase 3c: add block offsets, init cursors, close CSR ----
__global__ void k_scanC(int n, int nE) {
    for (int i = blockIdx.x * blockDim.x + threadIdx.x; i < n;
         i += gridDim.x * blockDim.x) {
        int o = g_off[i] + g_boff[i >> 10];
        g_off[i] = o;
        g_cur[i] = o;
    }
    if (blockIdx.x == 0 && threadIdx.x == 0) g_off[n] = nE;
}

// ---- Phase 4: scatter edges into row-sorted pair array ----
__global__ void k_scatter(const int* __restrict__ rows,
                          const int* __restrict__ cols,
                          const float* __restrict__ vals, int nE) {
    for (int e = blockIdx.x * blockDim.x + threadIdx.x; e < nE;
         e += gridDim.x * blockDim.x) {
        int r   = rows[e];
        int pos = atomicAdd(&g_cur[r], 1);
        g_pairs[pos] = make_int2(cols[e], __float_as_int(vals[e]));
    }
}

// ---- Phase 5: per-row register accumulation, one store per row ----
// 16 lanes per row (float4 each), 16 rows per 256-thread block.
__global__ void __launch_bounds__(256)
k_accum(const float* __restrict__ emb, float* __restrict__ out, int n) {
    int lane = threadIdx.x & 15;
    int slot = threadIdx.x >> 4;
    int row  = blockIdx.x * 16 + slot;
    if (row >= n) return;

    int s = g_off[row];
    int e = g_off[row + 1];

    float4 acc = make_float4(0.f, 0.f, 0.f, 0.f);

    int i = s;
    for (; i + 4 <= e; i += 4) {
        int2 p0 = g_pairs[i + 0];
        int2 p1 = g_pairs[i + 1];
        int2 p2 = g_pairs[i + 2];
        int2 p3 = g_pairs[i + 3];
        float4 g0 = reinterpret_cast<const float4*>(emb + (size_t)p0.x * D)[lane];
        float4 g1 = reinterpret_cast<const float4*>(emb + (size_t)p1.x * D)[lane];
        float4 g2 = reinterpret_cast<const float4*>(emb + (size_t)p2.x * D)[lane];
        float4 g3 = reinterpret_cast<const float4*>(emb + (size_t)p3.x * D)[lane];
        float v0 = __int_as_float(p0.y), v1 = __int_as_float(p1.y);
        float v2 = __int_as_float(p2.y), v3 = __int_as_float(p3.y);
        acc.x = fmaf(v0, g0.x, acc.x); acc.y = fmaf(v0, g0.y, acc.y);
        acc.z = fmaf(v0, g0.z, acc.z); acc.w = fmaf(v0, g0.w, acc.w);
        acc.x = fmaf(v1, g1.x, acc.x); acc.y = fmaf(v1, g1.y, acc.y);
        acc.z = fmaf(v1, g1.z, acc.z); acc.w = fmaf(v1, g1.w, acc.w);
        acc.x = fmaf(v2, g2.x, acc.x); acc.y = fmaf(v2, g2.y, acc.y);
        acc.z = fmaf(v2, g2.z, acc.z); acc.w = fmaf(v2, g2.w, acc.w);
        acc.x = fmaf(v3, g3.x, acc.x); acc.y = fmaf(v3, g3.y, acc.y);
        acc.z = fmaf(v3, g3.z, acc.z); acc.w = fmaf(v3, g3.w, acc.w);
    }
    for (; i < e; i++) {
        int2 p = g_pairs[i];
        float4 g = reinterpret_cast<const float4*>(emb + (size_t)p.x * D)[lane];
        float v = __int_as_float(p.y);
        acc.x = fmaf(v, g.x, acc.x); acc.y = fmaf(v, g.y, acc.y);
        acc.z = fmaf(v, g.z, acc.z); acc.w = fmaf(v, g.w, acc.w);
    }

    reinterpret_cast<float4*>(out + (size_t)row * D)[lane] = acc;
}

extern "C" void kernel_launch(void* const* d_in, const int* in_sizes, int n_in,
                              void* d_out, int out_size)
{
    const float* emb  = (const float*)d_in[0];   // [N, 64]
    const float* vals = (const float*)d_in[1];   // [E]
    const int*   rows = (const int*)  d_in[2];   // [E]
    const int*   cols = (const int*)  d_in[3];   // [E]
    float* out = (float*)d_out;                  // [N, 64]

    int nE = in_sizes[1];
    int nN = in_sizes[0] / D;

    int gEdge = (nE + 255) / 256;
    int gNode = (nN + 255) / 256;
    int nblk  = (nN + 1023) / 1024;              // scan blocks (<=128)

    k_zero   <<<gNode, 256>>>(nN);
    k_hist   <<<gEdge, 256>>>(rows, nE);
    k_scanA  <<<nblk, 1024>>>(nN);
    k_scanB  <<<1, 128>>>(nblk);
    k_scanC  <<<gNode, 256>>>(nN, nE);
    k_scatter<<<gEdge, 256>>>(rows, cols, vals, nE);
    k_accum  <<<(nN + 15) / 16, 256>>>(emb, out, nN);
}

// round 5
// speedup vs baseline: 1.1828x; 1.0358x over previous
#include <cuda_runtime.h>
#include <cstdint>

#define MAX_N 100000
#define MAX_E 1600000
#define D 64

#define SCAN_T 1024
#define SCAN_V 4
#define SCAN_TILE (SCAN_T * SCAN_V)   // 4096 -> 25 tiles for N=100000

// Zeroed-every-call scratch (single memset node covers all of it)
struct WS {
    int hist[MAX_N];                      // row degree histogram
    int cnt [MAX_N];                      // scatter cursors (start at 0)
    unsigned long long state[32];         // lookback state: (flag<<32)|value
};
__device__ WS   g_ws;
__device__ int  g_off[MAX_N + 1];         // CSR row offsets
__device__ int2 g_pairs[MAX_E];           // row-sorted (col, val_bits)

__device__ __forceinline__ unsigned long long ldv(const unsigned long long* p) {
    return *(volatile const unsigned long long*)p;
}
__device__ __forceinline__ void stv(unsigned long long* p, unsigned long long v) {
    *(volatile unsigned long long*)p = v;
}

// ---- Histogram (vectorized) ----
__global__ void k_hist(const int* __restrict__ rows, int nE) {
    int i = blockIdx.x * blockDim.x + threadIdx.x;
    int e = i * 4;
    if (e + 3 < nE) {
        int4 r = *reinterpret_cast<const int4*>(rows + e);
        atomicAdd(&g_ws.hist[r.x], 1);
        atomicAdd(&g_ws.hist[r.y], 1);
        atomicAdd(&g_ws.hist[r.z], 1);
        atomicAdd(&g_ws.hist[r.w], 1);
    } else {
        for (int k = e; k < nE; k++) atomicAdd(&g_ws.hist[rows[k]], 1);
    }
}

// ---- Single-pass decoupled-lookback exclusive scan -> g_off ----
__global__ void __launch_bounds__(SCAN_T)
k_scan(int n, int nE) {
    __shared__ int warp_sums[32];
    __shared__ int s_prefix;

    int b    = blockIdx.x;
    int t    = threadIdx.x;
    int lane = t & 31;
    int wid  = t >> 5;
    int idx  = b * SCAN_TILE + t * 4;

    // load 4 values
    int4 hv = make_int4(0, 0, 0, 0);
    if (idx + 3 < n) {
        hv = *reinterpret_cast<const int4*>(&g_ws.hist[idx]);
    } else if (idx < n) {
        hv.x = g_ws.hist[idx];
        if (idx + 1 < n) hv.y = g_ws.hist[idx + 1];
        if (idx + 2 < n) hv.z = g_ws.hist[idx + 2];
    }
    int tsum = hv.x + hv.y + hv.z + hv.w;

    // block-wide inclusive scan of per-thread sums
    int x = tsum;
    #pragma unroll
    for (int d = 1; d < 32; d <<= 1) {
        int y = __shfl_up_sync(~0u, x, d);
        if (lane >= d) x += y;
    }
    if (lane == 31) warp_sums[wid] = x;
    __syncthreads();
    if (wid == 0) {
        int s = warp_sums[lane];
        #pragma unroll
        for (int d = 1; d < 32; d <<= 1) {
            int y = __shfl_up_sync(~0u, s, d);
            if (lane >= d) s += y;
        }
        warp_sums[lane] = s;
    }
    __syncthreads();

    int texcl     = (x - tsum) + (wid > 0 ? warp_sums[wid - 1] : 0);
    int block_agg = warp_sums[31];

    // publish + lookback (warp 0)
    if (wid == 0) {
        if (b == 0) {
            if (lane == 0) {
                stv(&g_ws.state[0], (2ULL << 32) | (unsigned)block_agg);
                s_prefix = 0;
            }
        } else {
            if (lane == 0)
                stv(&g_ws.state[b], (1ULL << 32) | (unsigned)block_agg);
            // warp-parallel lookback: lane L inspects predecessor b-1-L
            int j = b - 1 - lane;
            int f = 2, v = 0;
            for (;;) {
                if (j >= 0) {
                    unsigned long long s = ldv(&g_ws.state[j]);
                    f = (int)(s >> 32);
                    v = (int)(unsigned)s;
                }
                if (__all_sync(~0u, f != 0)) break;
            }
            unsigned m2    = __ballot_sync(~0u, f == 2);
            int      first = __ffs(m2) - 1;                 // nearest PREFIX
            int contrib = (lane <= first) ? v : 0;
            #pragma unroll
            for (int d = 16; d > 0; d >>= 1)
                contrib += __shfl_down_sync(~0u, contrib, d);
            int ep = __shfl_sync(~0u, contrib, 0);          // exclusive prefix
            if (lane == 0) {
                stv(&g_ws.state[b], (2ULL << 32) | (unsigned)(ep + block_agg));
                s_prefix = ep;
            }
        }
    }
    __syncthreads();

    int bp = s_prefix;
    int o0 = bp + texcl;
    int o1 = o0 + hv.x;
    int o2 = o1 + hv.y;
    int o3 = o2 + hv.z;
    if (idx + 3 < n) {
        *reinterpret_cast<int4*>(&g_off[idx]) = make_int4(o0, o1, o2, o3);
    } else if (idx < n) {
        g_off[idx] = o0;
        if (idx + 1 < n) g_off[idx + 1] = o1;
        if (idx + 2 < n) g_off[idx + 2] = o2;
    }
    if (b == 0 && t == 0) g_off[n] = nE;
}

// ---- Scatter into row-sorted order ----
__global__ void k_scatter(const int* __restrict__ rows,
                          const int* __restrict__ cols,
                          const float* __restrict__ vals, int nE) {
    int e = blockIdx.x * blockDim.x + threadIdx.x;
    if (e >= nE) return;
    int r   = rows[e];
    int pos = g_off[r] + atomicAdd(&g_ws.cnt[r], 1);
    g_pairs[pos] = make_int2(cols[e], __float_as_int(vals[e]));
}

// ---- Accumulate: 16 lanes per row, register accumulation, one store ----
__global__ void __launch_bounds__(256)
k_accum(const float* __restrict__ emb, float* __restrict__ out, int n) {
    int lane = threadIdx.x & 15;
    int slot = threadIdx.x >> 4;
    int row  = blockIdx.x * 16 + slot;
    if (row >= n) return;

    int s = g_off[row];
    int e = g_off[row + 1];

    float4 acc = make_float4(0.f, 0.f, 0.f, 0.f);

    int i = s;
    for (; i + 4 <= e; i += 4) {
        int2 p0 = g_pairs[i + 0];
        int2 p1 = g_pairs[i + 1];
        int2 p2 = g_pairs[i + 2];
        int2 p3 = g_pairs[i + 3];
        float4 g0 = reinterpret_cast<const float4*>(emb + (size_t)p0.x * D)[lane];
        float4 g1 = reinterpret_cast<const float4*>(emb + (size_t)p1.x * D)[lane];
        float4 g2 = reinterpret_cast<const float4*>(emb + (size_t)p2.x * D)[lane];
        float4 g3 = reinterpret_cast<const float4*>(emb + (size_t)p3.x * D)[lane];
        float v0 = __int_as_float(p0.y), v1 = __int_as_float(p1.y);
        float v2 = __int_as_float(p2.y), v3 = __int_as_float(p3.y);
        acc.x = fmaf(v0, g0.x, acc.x); acc.y = fmaf(v0, g0.y, acc.y);
        acc.z = fmaf(v0, g0.z, acc.z); acc.w = fmaf(v0, g0.w, acc.w);
        acc.x = fmaf(v1, g1.x, acc.x); acc.y = fmaf(v1, g1.y, acc.y);
        acc.z = fmaf(v1, g1.z, acc.z); acc.w = fmaf(v1, g1.w, acc.w);
        acc.x = fmaf(v2, g2.x, acc.x); acc.y = fmaf(v2, g2.y, acc.y);
        acc.z = fmaf(v2, g2.z, acc.z); acc.w = fmaf(v2, g2.w, acc.w);
        acc.x = fmaf(v3, g3.x, acc.x); acc.y = fmaf(v3, g3.y, acc.y);
        acc.z = fmaf(v3, g3.z, acc.z); acc.w = fmaf(v3, g3.w, acc.w);
    }
    for (; i < e; i++) {
        int2 p = g_pairs[i];
        float4 g = reinterpret_cast<const float4*>(emb + (size_t)p.x * D)[lane];
        float v = __int_as_float(p.y);
        acc.x = fmaf(v, g.x, acc.x); acc.y = fmaf(v, g.y, acc.y);
        acc.z = fmaf(v, g.z, acc.z); acc.w = fmaf(v, g.w, acc.w);
    }

    reinterpret_cast<float4*>(out + (size_t)row * D)[lane] = acc;
}

extern "C" void kernel_launch(void* const* d_in, const int* in_sizes, int n_in,
                              void* d_out, int out_size)
{
    const float* emb  = (const float*)d_in[0];   // [N, 64]
    const float* vals = (const float*)d_in[1];   // [E]
    const int*   rows = (const int*)  d_in[2];   // [E]
    const int*   cols = (const int*)  d_in[3];   // [E]
    float* out = (float*)d_out;                  // [N, 64]

    int nE = in_sizes[1];
    int nN = in_sizes[0] / D;

    void* ws_ptr = nullptr;
    cudaGetSymbolAddress(&ws_ptr, g_ws);
    cudaMemsetAsync(ws_ptr, 0, sizeof(WS), 0);

    int gHist  = (nE / 4 + 255) / 256 + 1;
    int nTiles = (nN + SCAN_TILE - 1) / SCAN_TILE;   // 25 for N=100000 (<=32)
    int gEdge  = (nE + 255) / 256;

    k_hist   <<<gHist, 256>>>(rows, nE);
    k_scan   <<<nTiles, SCAN_T>>>(nN, nE);
    k_scatter<<<gEdge, 256>>>(rows, cols, vals, nE);
    k_accum  <<<(nN + 15) / 16, 256>>>(emb, out, nN);
}